// round 1
// baseline (speedup 1.0000x reference)
#include <cuda_runtime.h>
#include <math.h>

#define SEQ   4096
#define BATCH 16
#define DIM   1024
#define HID   512
#define LL    32
#define BD    (BATCH*DIM)   // 16384

// ---------------- scratch (static device memory; fully rewritten every launch) --
__device__ float g_partial[32][BD];            // per-s-chunk partial sums for context
__device__ float g_sp_h[BATCH][HID];           // gelu(ctx@w_sp1^T+b)
__device__ float g_ctx_part[BATCH][HID];       // ctx@w_rs1[:,D:]^T + b_rs1
__device__ float g_hist_pre[2][LL*BATCH][HID]; // hist@w_rs1[:,:D]^T (no bias)
__device__ float g_scores[2][LL][BATCH];
__device__ float g_span[BATCH][3];
__device__ float g_pool_feat[2][BATCH][DIM];
__device__ float g_fused_raw[BATCH][DIM];
__device__ float g_fused[BATCH][DIM];
__device__ float g_fg[BATCH][DIM];             // fused * gate

__device__ __forceinline__ float gelu_exact(float x){
    return 0.5f * x * (1.0f + erff(x * 0.70710678118654752440f));
}

// ---------------- K1: partial column sums of features over 128-row s-chunks -----
__global__ void __launch_bounds__(256) k_partial(const float* __restrict__ f){
    int col = blockIdx.x * 256 + threadIdx.x;       // 0..16383
    int sy  = blockIdx.y;                           // 0..31
    const float* p = f + (size_t)sy * 128 * BD + col;
    float s = 0.f;
    #pragma unroll 8
    for (int i = 0; i < 128; i++) s += p[(size_t)i * BD];
    g_partial[sy][col] = s;
}

// ---------------- K2: hist GEMM  (M=512, N=512, K=1024) x 2 pools ---------------
// out[pool][m][h] = sum_k A(pool,m,k) * w_rs1[h*2048 + k]
__global__ void __launch_bounds__(256) k_histgemm(const float* __restrict__ f,
                                                  const float* __restrict__ w_rs1){
    __shared__ __align__(16) float As[16][68];
    __shared__ __align__(16) float Bs[16][68];
    int pool = blockIdx.z;
    int m0 = blockIdx.y * 64, n0 = blockIdx.x * 64;
    int t = threadIdx.x;
    int lrow = t >> 2;          // 0..63
    int kq   = (t & 3) * 4;     // 0,4,8,12

    int m = m0 + lrow;
    size_t aoff = (pool == 0)
        ? (size_t)4064 * BD + (size_t)m * 1024
        : (size_t)(m >> 4) * 128 * BD + (size_t)(m & 15) * 1024;
    const float* aptr = f + aoff;
    const float* bptr = w_rs1 + (size_t)(n0 + lrow) * 2048;

    int tx = t & 15, ty = t >> 4;
    float acc[4][4] = {};

    for (int k0 = 0; k0 < 1024; k0 += 16){
        float4 av = *(const float4*)(aptr + k0 + kq);
        float4 bv = *(const float4*)(bptr + k0 + kq);
        __syncthreads();
        As[kq+0][lrow]=av.x; As[kq+1][lrow]=av.y; As[kq+2][lrow]=av.z; As[kq+3][lrow]=av.w;
        Bs[kq+0][lrow]=bv.x; Bs[kq+1][lrow]=bv.y; Bs[kq+2][lrow]=bv.z; Bs[kq+3][lrow]=bv.w;
        __syncthreads();
        #pragma unroll
        for (int kk = 0; kk < 16; kk++){
            float4 a = *(const float4*)&As[kk][ty*4];
            float4 b = *(const float4*)&Bs[kk][tx*4];
            acc[0][0] += a.x*b.x; acc[0][1] += a.x*b.y; acc[0][2] += a.x*b.z; acc[0][3] += a.x*b.w;
            acc[1][0] += a.y*b.x; acc[1][1] += a.y*b.y; acc[1][2] += a.y*b.z; acc[1][3] += a.y*b.w;
            acc[2][0] += a.z*b.x; acc[2][1] += a.z*b.y; acc[2][2] += a.z*b.z; acc[2][3] += a.z*b.w;
            acc[3][0] += a.w*b.x; acc[3][1] += a.w*b.y; acc[3][2] += a.w*b.z; acc[3][3] += a.w*b.w;
        }
    }
    #pragma unroll
    for (int i = 0; i < 4; i++)
        #pragma unroll
        for (int j = 0; j < 4; j++)
            g_hist_pre[pool][m0 + ty*4 + i][n0 + tx*4 + j] = acc[i][j];
}

// ---------------- K3: finalize context; sp_h; ctx_part --------------------------
__global__ void __launch_bounds__(256) k_ctx_mlps(const float* __restrict__ w_sp1,
                                                  const float* __restrict__ b_sp1,
                                                  const float* __restrict__ w_rs1,
                                                  const float* __restrict__ b_rs1){
    __shared__ __align__(16) float ctx[DIM];
    int b = blockIdx.x, y = blockIdx.y, t = threadIdx.x;
    for (int i = t; i < DIM; i += 256){
        float s = 0.f;
        #pragma unroll
        for (int j = 0; j < 32; j++) s += g_partial[j][b*1024 + i];
        ctx[i] = s * (1.0f/4096.0f);
    }
    __syncthreads();
    const float4* c4 = (const float4*)ctx;
    if (y < 2){
        int h = y*256 + t;
        const float4* w4 = (const float4*)(w_sp1 + (size_t)h*1024);
        float s = b_sp1[h];
        #pragma unroll 4
        for (int k = 0; k < 256; k++){
            float4 c = c4[k], w = w4[k];
            s += c.x*w.x + c.y*w.y + c.z*w.z + c.w*w.w;
        }
        g_sp_h[b][h] = gelu_exact(s);
    } else {
        int h = (y-2)*256 + t;
        const float4* w4 = (const float4*)(w_rs1 + (size_t)h*2048 + 1024);
        float s = b_rs1[h];
        #pragma unroll 4
        for (int k = 0; k < 256; k++){
            float4 c = c4[k], w = w4[k];
            s += c.x*w.x + c.y*w.y + c.z*w.z + c.w*w.w;
        }
        g_ctx_part[b][h] = s;
    }
}

// ---------------- K4: span weights (16x3 softmax) --------------------------------
__global__ void k_span(const float* __restrict__ w_sp2, const float* __restrict__ b_sp2){
    __shared__ float lg[BATCH][3];
    int t = threadIdx.x;
    if (t < 48){
        int b = t / 3, j = t % 3;
        const float* w = w_sp2 + j*HID;
        float s = b_sp2[j];
        for (int k = 0; k < HID; k++) s += g_sp_h[b][k] * w[k];
        lg[b][j] = s;
    }
    __syncthreads();
    if (t < BATCH){
        float a = lg[t][0], b2 = lg[t][1], c = lg[t][2];
        float m = fmaxf(a, fmaxf(b2, c));
        float ea = expf(a-m), eb = expf(b2-m), ec = expf(c-m);
        float inv = 1.0f / (ea + eb + ec);
        g_span[t][0] = ea*inv; g_span[t][1] = eb*inv; g_span[t][2] = ec*inv;
    }
}

// ---------------- K5: pool scores ------------------------------------------------
__global__ void __launch_bounds__(256) k_scores(const float* __restrict__ w_rs2,
                                                const float* __restrict__ b_rs2){
    int b = blockIdx.x, l = blockIdx.y, pool = blockIdx.z;
    int t = threadIdx.x;
    float s = 0.f;
    for (int h = t; h < HID; h += 256){
        float v = g_hist_pre[pool][l*16 + b][h] + g_ctx_part[b][h];
        s += gelu_exact(v) * w_rs2[h];
    }
    __shared__ float red[8];
    int lane = t & 31, w = t >> 5;
    #pragma unroll
    for (int o = 16; o > 0; o >>= 1) s += __shfl_xor_sync(0xffffffffu, s, o);
    if (lane == 0) red[w] = s;
    __syncthreads();
    if (t == 0){
        float acc = 0.f;
        #pragma unroll
        for (int i = 0; i < 8; i++) acc += red[i];
        g_scores[pool][l][b] = acc + b_rs2[0];
    }
}

// ---------------- K6: decay softmax + weighted sum of hist ------------------------
__global__ void __launch_bounds__(256) k_pool(const float* __restrict__ f,
                                              const float* __restrict__ decay_l,
                                              const float* __restrict__ decay_g){
    int b = blockIdx.x, pool = blockIdx.y;
    int t = threadIdx.x;
    __shared__ float wgt[LL];
    if (t == 0){
        float dec = (pool == 0) ? decay_l[0] : decay_g[0];
        float tv[LL]; float mx = -1e30f;
        for (int l = 0; l < LL; l++){
            float d = powf(dec, (float)(LL - 1 - l));
            tv[l] = g_scores[pool][l][b] + logf(d + 1e-8f);
            mx = fmaxf(mx, tv[l]);
        }
        float ssum = 0.f;
        for (int l = 0; l < LL; l++){ float e = expf(tv[l] - mx); wgt[l] = e; ssum += e; }
        float inv = 1.0f / ssum;
        for (int l = 0; l < LL; l++) wgt[l] *= inv;
    }
    __syncthreads();
    for (int d = t; d < DIM; d += 256){
        float acc = 0.f;
        #pragma unroll
        for (int l = 0; l < LL; l++){
            size_t off = (pool == 0) ? (size_t)(4064 + l) * BD : (size_t)l * 128 * BD;
            acc += wgt[l] * f[off + (size_t)b*1024 + d];
        }
        g_pool_feat[pool][b][d] = acc;
    }
}

// ---------------- K7: fused = gelu(combined @ w_ff^T + b_ff) ----------------------
__global__ void __launch_bounds__(256) k_fusedpre(const float* __restrict__ w_ff,
                                                  const float* __restrict__ b_ff){
    __shared__ __align__(16) float comb[2*DIM];
    int b = blockIdx.x, t = threadIdx.x;
    float s1 = g_span[b][1], s2 = g_span[b][2];
    for (int i = t; i < 2*DIM; i += 256)
        comb[i] = (i < DIM) ? g_pool_feat[0][b][i] * s1 : g_pool_feat[1][b][i-DIM] * s2;
    __syncthreads();
    int j = blockIdx.y * 256 + t;
    const float4* c4 = (const float4*)comb;
    const float4* w4 = (const float4*)(w_ff + (size_t)j * 2048);
    float s = b_ff[j];
    #pragma unroll 4
    for (int k = 0; k < 512; k++){
        float4 c = c4[k], w = w4[k];
        s += c.x*w.x + c.y*w.y + c.z*w.z + c.w*w.w;
    }
    g_fused_raw[b][j] = gelu_exact(s);
}

// ---------------- K8: layernorm(fused_raw) ----------------------------------------
__global__ void __launch_bounds__(256) k_lnfused(const float* __restrict__ g,
                                                 const float* __restrict__ be){
    int b = blockIdx.x, t = threadIdx.x;
    float sum = 0.f, ss = 0.f;
    float v[4];
    #pragma unroll
    for (int i = 0; i < 4; i++){
        v[i] = g_fused_raw[b][t + i*256];
        sum += v[i]; ss += v[i]*v[i];
    }
    __shared__ float rs_s[8], rs_q[8];
    int lane = t & 31, w = t >> 5;
    #pragma unroll
    for (int o = 16; o > 0; o >>= 1){
        sum += __shfl_xor_sync(0xffffffffu, sum, o);
        ss  += __shfl_xor_sync(0xffffffffu, ss, o);
    }
    if (lane == 0){ rs_s[w] = sum; rs_q[w] = ss; }
    __syncthreads();
    float tsum = 0.f, tss = 0.f;
    #pragma unroll
    for (int i = 0; i < 8; i++){ tsum += rs_s[i]; tss += rs_q[i]; }
    float mu = tsum * (1.0f/1024.0f);
    float var = tss * (1.0f/1024.0f) - mu*mu;
    float rstd = rsqrtf(var + 1e-5f);
    #pragma unroll
    for (int i = 0; i < 4; i++){
        int j = t + i*256;
        g_fused[b][j] = (v[i] - mu) * rstd * g[j] + be[j];
    }
}

// ---------------- K9: gate, fg = fused * sigmoid(fused @ w_gate^T + b_gate) -------
__global__ void __launch_bounds__(256) k_gate(const float* __restrict__ w_gate,
                                              const float* __restrict__ b_gate){
    __shared__ __align__(16) float fu[DIM];
    int b = blockIdx.x, t = threadIdx.x;
    for (int i = t; i < DIM; i += 256) fu[i] = g_fused[b][i];
    __syncthreads();
    int j = blockIdx.y * 256 + t;
    const float4* c4 = (const float4*)fu;
    const float4* w4 = (const float4*)(w_gate + (size_t)j * 1024);
    float s = b_gate[j];
    #pragma unroll 4
    for (int k = 0; k < 256; k++){
        float4 c = c4[k], w = w4[k];
        s += c.x*w.x + c.y*w.y + c.z*w.z + c.w*w.w;
    }
    float gate = 1.0f / (1.0f + expf(-s));
    g_fg[b][j] = fu[j] * gate;
}

// ---------------- K10: big pass — output = LN(features + fg[b]) -------------------
__global__ void __launch_bounds__(256) k_bigln(const float* __restrict__ f,
                                               const float* __restrict__ ln_g,
                                               const float* __restrict__ ln_b,
                                               float* __restrict__ out){
    int warp = threadIdx.x >> 5, lane = threadIdx.x & 31;
    int row = blockIdx.x * 8 + warp;     // row = s*16 + b
    int b = row & 15;
    const float4* x4  = (const float4*)(f + (size_t)row * DIM);
    const float4* fg4 = (const float4*)(&g_fg[b][0]);
    float4 v[8];
    float sum = 0.f, ss = 0.f;
    #pragma unroll
    for (int i = 0; i < 8; i++){
        float4 a = x4[lane + i*32];
        float4 c = fg4[lane + i*32];
        float4 tv;
        tv.x = a.x + c.x; tv.y = a.y + c.y; tv.z = a.z + c.z; tv.w = a.w + c.w;
        v[i] = tv;
        sum += tv.x + tv.y + tv.z + tv.w;
        ss  += tv.x*tv.x + tv.y*tv.y + tv.z*tv.z + tv.w*tv.w;
    }
    #pragma unroll
    for (int o = 16; o > 0; o >>= 1){
        sum += __shfl_xor_sync(0xffffffffu, sum, o);
        ss  += __shfl_xor_sync(0xffffffffu, ss, o);
    }
    float mu = sum * (1.0f/1024.0f);
    float var = ss * (1.0f/1024.0f) - mu*mu;
    float rstd = rsqrtf(var + 1e-5f);
    float4* o4 = (float4*)(out + (size_t)row * DIM);
    const float4* g4 = (const float4*)ln_g;
    const float4* b4 = (const float4*)ln_b;
    #pragma unroll
    for (int i = 0; i < 8; i++){
        float4 g = g4[lane + i*32], be = b4[lane + i*32], tv = v[i], r;
        r.x = (tv.x - mu)*rstd*g.x + be.x;
        r.y = (tv.y - mu)*rstd*g.y + be.y;
        r.z = (tv.z - mu)*rstd*g.z + be.z;
        r.w = (tv.w - mu)*rstd*g.w + be.w;
        o4[lane + i*32] = r;
    }
}

// ---------------- K11: attention weights fill --------------------------------------
__global__ void k_aw(float* __restrict__ aw){
    aw[blockIdx.x * 256 + threadIdx.x] = 1.0f / 4096.0f;
}

// ---------------- launcher ---------------------------------------------------------
extern "C" void kernel_launch(void* const* d_in, const int* in_sizes, int n_in,
                              void* d_out, int out_size){
    const float* features = (const float*)d_in[0];
    const float* w_sp1    = (const float*)d_in[1];
    const float* b_sp1    = (const float*)d_in[2];
    const float* w_sp2    = (const float*)d_in[3];
    const float* b_sp2    = (const float*)d_in[4];
    const float* w_rs1    = (const float*)d_in[5];
    const float* b_rs1    = (const float*)d_in[6];
    const float* w_rs2    = (const float*)d_in[7];
    const float* b_rs2    = (const float*)d_in[8];
    const float* decay_l  = (const float*)d_in[9];
    const float* decay_g  = (const float*)d_in[10];
    const float* w_ff     = (const float*)d_in[11];
    const float* b_ff     = (const float*)d_in[12];
    const float* ln_ff_g  = (const float*)d_in[13];
    const float* ln_ff_b  = (const float*)d_in[14];
    const float* w_gate   = (const float*)d_in[15];
    const float* b_gate   = (const float*)d_in[16];
    const float* ln_g     = (const float*)d_in[17];
    const float* ln_b     = (const float*)d_in[18];
    float* out = (float*)d_out;
    float* out_aw = out + (size_t)SEQ * BATCH * DIM;

    // context partial sums (independent of GEMM)
    k_partial<<<dim3(64, 32), 256>>>(features);
    // hist GEMM (independent of context)
    k_histgemm<<<dim3(8, 8, 2), 256>>>(features, w_rs1);
    // context finalize + small MLPs
    k_ctx_mlps<<<dim3(16, 4), 256>>>(w_sp1, b_sp1, w_rs1, b_rs1);
    k_span<<<1, 64>>>(w_sp2, b_sp2);
    k_scores<<<dim3(16, 32, 2), 256>>>(w_rs2, b_rs2);
    k_pool<<<dim3(16, 2), 256>>>(features, decay_l, decay_g);
    k_fusedpre<<<dim3(16, 4), 256>>>(w_ff, b_ff);
    k_lnfused<<<16, 256>>>(ln_ff_g, ln_ff_b);
    k_gate<<<dim3(16, 4), 256>>>(w_gate, b_gate);
    // big output pass
    k_bigln<<<8192, 256>>>(features, ln_g, ln_b, out);
    k_aw<<<256, 256>>>(out_aw);
}